// round 2
// baseline (speedup 1.0000x reference)
#include <cuda_runtime.h>
#include <math.h>

// x: (8, 256, 32, 32) f32 ; weight: (8, 36, 64) f32 ; out: (8, 512, 32, 32) f32
// Semantics (matching reference's flat reshape):
//   per batch b, output "row" r in [0,1024):
//     v[j] = xu_flat[b, 2304*r + j], j in [0,2304), xu_flat = unfold(x) flattened
//            feature-major: flat = i*1024 + l, i = c*9 + di*3+dj, l = lh*32+lw
//     vb = v.reshape(36, 64); out[b, p*64+n, r] = irfft( sum_q rfft(vb[q]) * rfft(W[p,q]) )[n]
#define NQ 36
#define NP 8
#define NF 33

__device__ float g_WF[NQ * NP * NF * 2];

__global__ void prep_kernel(const float* __restrict__ w) {
    int idx = blockIdx.x * blockDim.x + threadIdx.x;
    if (idx >= NQ * NP * NF) return;
    int f  = idx % NF;
    int pq = idx / NF;
    int p  = pq % NP;
    int q  = pq / NP;
    const float* wp = w + (p * NQ + q) * 64;
    float re = 0.f, im = 0.f;
    for (int m = 0; m < 64; m++) {
        int t = (f * m) & 63;
        float s, c;
        sincosf(-(float)t * 0.0981747704246810387f, &s, &c);
        re = fmaf(wp[m], c, re);
        im = fmaf(wp[m], s, im);
    }
    g_WF[idx * 2]     = re;
    g_WF[idx * 2 + 1] = im;
}

// smem float offsets
#define SZ_WF    (NQ * NP * NF * 2)      // 19008
#define U_STRIDE 2640                    // per-warp union region (floats)
#define SZ_U     (8 * U_STRIDE)          // 21120 (xu padded 2376 ⊎ XF 2376 @ +264; reused as ytile)
#define SZ_HF    (8 * NP * NF * 2)       // 4224
#define SZ_TW    66
#define OFF_WF   0
#define OFF_U    (OFF_WF + SZ_WF)
#define OFF_HF   (OFF_U + SZ_U)
#define OFF_TW   (OFF_HF + SZ_HF)
#define SMEM_FLOATS (OFF_TW + SZ_TW)     // 44418 floats = 177672 B

__global__ void __launch_bounds__(256, 1)
bcconv_kernel(const float* __restrict__ x, float* __restrict__ out) {
    extern __shared__ float smem[];
    float* sWF = smem + OFF_WF;
    float* sU  = smem + OFF_U;
    float* sHF = smem + OFF_HF;
    float* sTW = smem + OFF_TW;

    const int tid  = threadIdx.x;
    const int wid  = tid >> 5;
    const int lane = tid & 31;
    const int bi   = blockIdx.x;
    const int b    = bi >> 7;
    const int grp  = bi & 127;
    const int r0   = grp << 3;          // 8 consecutive output rows per CTA
    const int h    = r0 >> 5;
    const int w0   = r0 & 31;

    // twiddles: tw[k] = (cos, sin)(2*pi*k/64), k=0..32
    if (tid < 33) {
        float s, c;
        sincosf((float)tid * 0.0981747704246810387f, &s, &c);
        sTW[2 * tid]     = c;
        sTW[2 * tid + 1] = s;
    }
    // stage frequency-domain weights
    for (int i = tid; i < SZ_WF; i += 256) sWF[i] = g_WF[i];

    // per-warp union region: xu (padded: block q at q*66, 64 data + 2 pad)
    float* myU  = sU + wid * U_STRIDE;
    float* xu   = myU;
    float* myXF = myU + 264;            // XF: q*66 + 2f (re,im)
    float* myHF = sHF + wid * (NP * NF * 2);

    // ---------- gather this warp's 2304-element flat slice ----------
    {
        const int r = r0 + wid;
        for (int j = lane; j < 2304; j += 32) {
            int g  = r * 2304 + j;      // flat index within batch
            int i  = g >> 10;           // feature row (0..2303)
            int l  = g & 1023;          // pixel
            int c  = i / 9;
            int t  = i - c * 9;
            int gh = (l >> 5) - 1 + t / 3;
            int gw = (l & 31) - 1 + t % 3;
            float v = 0.f;
            if ((unsigned)gh < 32u && (unsigned)gw < 32u)
                v = x[((b * 256 + c) * 32 + gh) * 32 + gw];
            xu[(j >> 6) * 66 + (j & 63)] = v;
        }
    }
    __syncthreads();   // covers xu (own warp), sTW, sWF

    // ---------- forward rfft64 per 64-block (one block per lane) ----------
    // Round A (q = 32+lane, lanes 0..3) first: reads xu[2112..2376), writes XF[2376..2640) (disjoint).
    // Round B (q = lane): reads xu[0..2112), writes XF[264..2376) — syncwarp'd load->store.
    for (int round = 0; round < 2; round++) {
        int q = (round == 0) ? (32 + lane) : lane;
        float zr[32], zi[32];
        bool active = (q < NQ);
        if (active) {
            const float2* src = (const float2*)(xu) + q * 33;  // q*66 floats
#pragma unroll
            for (int m = 0; m < 32; m++) {
                float2 v = src[m];
                zr[m] = v.x;
                zi[m] = v.y;
            }
        }
        if (round == 1) __syncwarp();   // all loads done before overlapping stores
        if (active) {
            // FFT32 DIF radix-2, natural in / bit-reversed out
#pragma unroll
            for (int s = 0; s < 5; s++) {
                const int half = 16 >> s;
#pragma unroll
                for (int g = 0; g < (1 << s); g++) {
#pragma unroll
                    for (int j = 0; j < half; j++) {
                        int a  = g * (half * 2) + j;
                        int bb = a + half;
                        float tr = zr[a] - zr[bb];
                        float ti = zi[a] - zi[bb];
                        zr[a] += zr[bb];
                        zi[a] += zi[bb];
                        int t = j << (s + 1);
                        float c  = sTW[2 * t];
                        float sn = sTW[2 * t + 1];
                        zr[bb] = tr * c + ti * sn;
                        zi[bb] = ti * c - tr * sn;
                    }
                }
            }
            constexpr int rev[32] = {0,16,8,24,4,20,12,28,2,18,10,26,6,22,14,30,
                                     1,17,9,25,5,21,13,29,3,19,11,27,7,23,15,31};
#pragma unroll
            for (int k = 0; k < 32; k++) {
                int kc = (32 - k) & 31;
                float Zkr = zr[rev[k]],  Zki = zi[rev[k]];
                float Zcr = zr[rev[kc]], Zci = -zi[rev[kc]];
                float Fer = 0.5f * (Zkr + Zcr);
                float Fei = 0.5f * (Zki + Zci);
                float For = 0.5f * (Zki - Zci);
                float Foi = -0.5f * (Zkr - Zcr);
                float c  = sTW[2 * k];
                float sn = sTW[2 * k + 1];
                myXF[q * 66 + 2 * k]     = Fer + c * For + sn * Foi;
                myXF[q * 66 + 2 * k + 1] = Fei + c * Foi - sn * For;
            }
            myXF[q * 66 + 64] = zr[0] - zi[0];
            myXF[q * 66 + 65] = 0.f;
        }
        __syncwarp();
    }

    // ---------- freq-domain matvec: hf[p][f] = sum_q xf[q][f] * wf[q][p][f] ----------
    {
        float ar[NP], ai[NP];
#pragma unroll
        for (int p = 0; p < NP; p++) { ar[p] = 0.f; ai[p] = 0.f; }
        const float2* xf2 = (const float2*)myXF;      // [q*33 + f]
        const float2* wf2 = (const float2*)sWF;       // [(q*8+p)*33 + f]
        for (int q = 0; q < NQ; q++) {
            float2 xv = xf2[q * 33 + lane];
#pragma unroll
            for (int p = 0; p < NP; p++) {
                float2 wv = wf2[(q * NP + p) * NF + lane];
                ar[p] = fmaf(xv.x, wv.x, fmaf(-xv.y, wv.y, ar[p]));
                ai[p] = fmaf(xv.x, wv.y, fmaf( xv.y, wv.x, ai[p]));
            }
        }
#pragma unroll
        for (int p = 0; p < NP; p++) {
            myHF[(p * NF + lane) * 2]     = ar[p];
            myHF[(p * NF + lane) * 2 + 1] = ai[p];
        }
        // f = 32 (pure real): warp-reduced dot over q (q = lane, +4 extra)
#pragma unroll
        for (int p = 0; p < NP; p++) {
            float s = myXF[lane * 66 + 64] * sWF[((lane * NP + p) * NF + 32) * 2];
            if (lane < 4) {
                int q2 = lane + 32;
                s += myXF[q2 * 66 + 64] * sWF[((q2 * NP + p) * NF + 32) * 2];
            }
#pragma unroll
            for (int o = 16; o > 0; o >>= 1) s += __shfl_xor_sync(0xffffffffu, s, o);
            if (lane == 0) {
                myHF[(p * NF + 32) * 2]     = s;
                myHF[(p * NF + 32) * 2 + 1] = 0.f;
            }
        }
    }
    __syncthreads();   // all XF reads done -> union region becomes ytile [512][9]

    // ---------- inverse rfft64: lane handles n=lane and n=lane+32 ----------
    {
        float* yt = sU;
        float base_s = (lane & 1) ? -1.f : 1.f;
        float S0[NP], S1[NP], B0[NP];
#pragma unroll
        for (int p = 0; p < NP; p++) {
            float H0  = myHF[(p * NF + 0) * 2];
            float H32 = myHF[(p * NF + 32) * 2];
            B0[p] = H0 + base_s * H32;
            S0[p] = 0.f;
            S1[p] = 0.f;
        }
        float rc = sTW[2 * lane], rs = sTW[2 * lane + 1]; // e^{+2*pi*i*n/64}
        float cr = rc, ci = rs;
        float sgn = -1.f;
        for (int f = 1; f < 32; f++) {
#pragma unroll
            for (int p = 0; p < NP; p++) {
                float Hr = myHF[(p * NF + f) * 2];
                float Hi = myHF[(p * NF + f) * 2 + 1];
                float t = fmaf(Hr, cr, -Hi * ci);
                S0[p] += t;
                S1[p] = fmaf(sgn, t, S1[p]);
            }
            float ncr = cr * rc - ci * rs;
            float nci = cr * rs + ci * rc;
            cr = ncr; ci = nci;
            sgn = -sgn;
        }
        const float inv64 = 0.015625f;
#pragma unroll
        for (int p = 0; p < NP; p++) {
            yt[(p * 64 + lane) * 9 + wid]      = (B0[p] + 2.f * S0[p]) * inv64;
            yt[(p * 64 + lane + 32) * 9 + wid] = (B0[p] + 2.f * S1[p]) * inv64;
        }
    }
    __syncthreads();

    // coalesced transposed output write: out[b, ch, h, w0+px]
    for (int i = tid; i < 4096; i += 256) {
        int ch = i >> 3;
        int px = i & 7;
        out[((b * 512 + ch) * 32 + h) * 32 + w0 + px] = sU[ch * 9 + px];
    }
}

extern "C" void kernel_launch(void* const* d_in, const int* in_sizes, int n_in,
                              void* d_out, int out_size) {
    const float* x = (const float*)d_in[0];
    const float* w = (const float*)d_in[1];
    float* out = (float*)d_out;

    cudaFuncSetAttribute(bcconv_kernel,
                         cudaFuncAttributeMaxDynamicSharedMemorySize,
                         SMEM_FLOATS * (int)sizeof(float));

    prep_kernel<<<(NQ * NP * NF + 255) / 256, 256>>>(w);
    bcconv_kernel<<<1024, 256, SMEM_FLOATS * sizeof(float)>>>(x, out);
}

// round 3
// speedup vs baseline: 1.3068x; 1.3068x over previous
#include <cuda_runtime.h>
#include <math.h>

// x: (8, 256, 32, 32) f32 ; weight: (8, 36, 64) f32 ; out: (8, 512, 32, 32) f32
#define NQ 36
#define NP 8
#define NF 33
#define NW 12              // warps (=rows) per CTA
#define NTHREADS (NW * 32)
#define CHUNKS 86          // ceil(1024 / NW)

__device__ float g_WF[NQ * NP * NF * 2];

__global__ void prep_kernel(const float* __restrict__ w) {
    int idx = blockIdx.x * blockDim.x + threadIdx.x;
    if (idx >= NQ * NP * NF) return;
    int f  = idx % NF;
    int pq = idx / NF;
    int p  = pq % NP;
    int q  = pq / NP;
    const float* wp = w + (p * NQ + q) * 64;
    float re = 0.f, im = 0.f;
    for (int m = 0; m < 64; m++) {
        int t = (f * m) & 63;
        float s, c;
        sincosf(-(float)t * 0.0981747704246810387f, &s, &c);
        re = fmaf(wp[m], c, re);
        im = fmaf(wp[m], s, im);
    }
    g_WF[idx * 2]     = re;
    g_WF[idx * 2 + 1] = im;
}

// compile-time twiddles: cos(k*pi/32), k=0..32; sin(k) = cos(|k-16|)
__device__ constexpr float TWC[33] = {
    1.0f, 0.9951847266721969f, 0.9807852804032304f, 0.9569403357322088f,
    0.9238795325112867f, 0.8819212643483551f, 0.8314696123025452f, 0.7730104533627370f,
    0.7071067811865476f, 0.6343932841636455f, 0.5555702330196022f, 0.4713967368259976f,
    0.3826834323650898f, 0.2902846772544624f, 0.1950903220161283f, 0.0980171403295606f,
    0.0f, -0.0980171403295606f, -0.1950903220161283f, -0.2902846772544624f,
    -0.3826834323650898f, -0.4713967368259976f, -0.5555702330196022f, -0.6343932841636455f,
    -0.7071067811865476f, -0.7730104533627370f, -0.8314696123025452f, -0.8819212643483551f,
    -0.9238795325112867f, -0.9569403357322088f, -0.9807852804032304f, -0.9951847266721969f,
    -1.0f };
__device__ constexpr float twc(int k) { return TWC[k]; }
__device__ constexpr float tws(int k) { return TWC[k < 16 ? 16 - k : k - 16]; }

// smem float offsets
#define SZ_WF    (NQ * NP * NF * 2)          // 19008
#define U_STRIDE (NQ * 66)                   // 2376, XF in-place over xu
#define SZ_U     (NW * U_STRIDE)             // 28512
#define SZ_HF    (NW * NP * NF * 2)          // 6336
#define OFF_WF   0
#define OFF_U    (OFF_WF + SZ_WF)
#define OFF_HF   (OFF_U + SZ_U)
#define SMEM_FLOATS (OFF_HF + SZ_HF)         // 53856 floats = 215424 B

__global__ void __launch_bounds__(NTHREADS, 1)
bcconv_kernel(const float* __restrict__ x, float* __restrict__ out) {
    extern __shared__ float smem[];
    float* sWF = smem + OFF_WF;
    float* sU  = smem + OFF_U;
    float* sHF = smem + OFF_HF;

    const int tid  = threadIdx.x;
    const int wid  = tid >> 5;
    const int lane = tid & 31;
    const int bi   = blockIdx.x;
    const int b    = bi / CHUNKS;
    const int l0   = (bi - b * CHUNKS) * NW;    // first row (pixel) of this CTA
    const int r    = l0 + wid;                  // this warp's row within batch
    const bool active = (r < 1024);

    // stage frequency weights (float4)
    {
        const float4* src = (const float4*)g_WF;
        float4* dst = (float4*)sWF;
        for (int i = tid; i < SZ_WF / 4; i += NTHREADS) dst[i] = src[i];
    }

    float* xu   = sU + wid * U_STRIDE;   // also XF (in-place)
    float* myHF = sHF + wid * (NP * NF * 2);

    // ---------- gather 2304-float flat slice for this warp's row ----------
    if (active) {
        int G = r * 2304 + lane;
        int l = G & 1023;
        int i = G >> 10;
        int c = i / 9;
        int t = i - c * 9;
        int t3 = t / 3;
        int dh = t3 - 1, dw = t - t3 * 3 - 1;
        const float* xc = x + ((b << 8) + c) * 1024;
        int j = lane;
#pragma unroll 8
        for (int k = 0; k < 72; ++k) {
            int gh = (l >> 5) + dh;
            int gw = (l & 31) + dw;
            float v = 0.f;
            if ((unsigned)gh < 32u && (unsigned)gw < 32u)
                v = __ldg(xc + (gh << 5) + gw);
            xu[(j >> 6) * 66 + (j & 63)] = v;
            j += 32;
            l += 32;
            if (l >= 1024) {
                l -= 1024;
                if (++t == 9) { t = 0; xc += 1024; }
                t3 = t / 3;
                dh = t3 - 1; dw = t - t3 * 3 - 1;
            }
        }
    }
    __syncthreads();

    // ---------- CTA-wide forward rfft64: 432 blocks over 384 threads ----------
    // block B = local_row * 36 + q lives at sU + B*66 (since U_STRIDE = 36*66)
    for (int round = 0; round < 2; round++) {
        int B = round * NTHREADS + tid;
        if (B < NW * NQ) {
            float* base = sU + B * 66;
            float zr[32], zi[32];
            const float2* src = (const float2*)base;
#pragma unroll
            for (int m = 0; m < 32; m++) {
                float2 v = src[m];
                zr[m] = v.x;
                zi[m] = v.y;
            }
            // FFT32 DIF radix-2, natural in / bit-reversed out, immediate twiddles
#pragma unroll
            for (int s = 0; s < 5; s++) {
                const int half = 16 >> s;
#pragma unroll
                for (int g = 0; g < (1 << s); g++) {
#pragma unroll
                    for (int j = 0; j < half; j++) {
                        int a  = g * (half * 2) + j;
                        int bb = a + half;
                        float tr = zr[a] - zr[bb];
                        float ti = zi[a] - zi[bb];
                        zr[a] += zr[bb];
                        zi[a] += zi[bb];
                        const float c  = twc(j << (s + 1));
                        const float sn = tws(j << (s + 1));
                        zr[bb] = tr * c + ti * sn;
                        zi[bb] = ti * c - tr * sn;
                    }
                }
            }
            constexpr int rev[32] = {0,16,8,24,4,20,12,28,2,18,10,26,6,22,14,30,
                                     1,17,9,25,5,21,13,29,3,19,11,27,7,23,15,31};
            float x32 = zr[0] - zi[0];
#pragma unroll
            for (int k = 0; k < 32; k++) {
                int kc = (32 - k) & 31;
                float Zkr = zr[rev[k]],  Zki = zi[rev[k]];
                float Zcr = zr[rev[kc]], Zci = -zi[rev[kc]];
                float Fer = 0.5f * (Zkr + Zcr);
                float Fei = 0.5f * (Zki + Zci);
                float For = 0.5f * (Zki - Zci);
                float Foi = -0.5f * (Zkr - Zcr);
                const float c  = twc(k);
                const float sn = tws(k);
                base[2 * k]     = Fer + c * For + sn * Foi;
                base[2 * k + 1] = Fei + c * Foi - sn * For;
            }
            base[64] = x32;
            base[65] = 0.f;
        }
    }
    __syncthreads();

    // ---------- freq-domain matvec: hf[p][f] = sum_q xf[q][f] * wf[q][p][f] ----------
    if (active) {
        float ar[NP], ai[NP];
#pragma unroll
        for (int p = 0; p < NP; p++) { ar[p] = 0.f; ai[p] = 0.f; }
        const float2* xf2 = (const float2*)xu;        // [q*33 + f]
        const float2* wf2 = (const float2*)sWF;       // [(q*8+p)*33 + f]
        for (int q = 0; q < NQ; q++) {
            float2 xv = xf2[q * 33 + lane];
#pragma unroll
            for (int p = 0; p < NP; p++) {
                float2 wv = wf2[(q * NP + p) * NF + lane];
                ar[p] = fmaf(xv.x, wv.x, fmaf(-xv.y, wv.y, ar[p]));
                ai[p] = fmaf(xv.x, wv.y, fmaf( xv.y, wv.x, ai[p]));
            }
        }
#pragma unroll
        for (int p = 0; p < NP; p++) {
            myHF[(p * NF + lane) * 2]     = ar[p];
            myHF[(p * NF + lane) * 2 + 1] = ai[p];
        }
        // f = 32 (pure real): warp-reduced dot over q
#pragma unroll
        for (int p = 0; p < NP; p++) {
            float s = xu[lane * 66 + 64] * sWF[((lane * NP + p) * NF + 32) * 2];
            if (lane < 4) {
                int q2 = lane + 32;
                s += xu[q2 * 66 + 64] * sWF[((q2 * NP + p) * NF + 32) * 2];
            }
#pragma unroll
            for (int o = 16; o > 0; o >>= 1) s += __shfl_xor_sync(0xffffffffu, s, o);
            if (lane == 0) {
                myHF[(p * NF + 32) * 2]     = s;
                myHF[(p * NF + 32) * 2 + 1] = 0.f;
            }
        }
    }
    __syncthreads();   // all XF reads done -> sU becomes ytile [512][13]

    // ---------- inverse rfft64: lane handles n=lane and n=lane+32, all 8 p ----------
    if (active) {
        float* yt = sU;                      // [512][13], px stride 13 (conflict-free)
        float base_s = (lane & 1) ? -1.f : 1.f;
        float S0[NP], S1[NP], B0[NP];
#pragma unroll
        for (int p = 0; p < NP; p++) {
            float H0  = myHF[(p * NF + 0) * 2];
            float H32 = myHF[(p * NF + 32) * 2];
            B0[p] = H0 + base_s * H32;
            S0[p] = 0.f;
            S1[p] = 0.f;
        }
        float rc, rs;
        sincosf((float)lane * 0.0981747704246810387f, &rs, &rc); // e^{+2pi i n/64}
        float cr = rc, ci = rs;
        float sgn = -1.f;
        for (int f = 1; f < 32; f++) {
#pragma unroll
            for (int p = 0; p < NP; p++) {
                float Hr = myHF[(p * NF + f) * 2];
                float Hi = myHF[(p * NF + f) * 2 + 1];
                float t = fmaf(Hr, cr, -Hi * ci);
                S0[p] += t;
                S1[p] = fmaf(sgn, t, S1[p]);
            }
            float ncr = cr * rc - ci * rs;
            float nci = cr * rs + ci * rc;
            cr = ncr; ci = nci;
            sgn = -sgn;
        }
        const float inv64 = 0.015625f;
#pragma unroll
        for (int p = 0; p < NP; p++) {
            yt[(p * 64 + lane) * 13 + wid]        = (B0[p] + 2.f * S0[p]) * inv64;
            yt[(p * 64 + lane + 32) * 13 + wid]   = (B0[p] + 2.f * S1[p]) * inv64;
        }
    }
    __syncthreads();

    // ---------- output write: out[b, ch, l0+px] ----------
    {
        float* yt = sU;
        const int obase = (b * 512) * 1024 + l0;
        for (int i = tid; i < 512 * NW; i += NTHREADS) {
            int ch = i / NW;
            int px = i - ch * NW;
            int l  = l0 + px;
            if (l < 1024)
                out[obase - l0 + ch * 1024 + l] = yt[ch * 13 + px];
        }
    }
}

extern "C" void kernel_launch(void* const* d_in, const int* in_sizes, int n_in,
                              void* d_out, int out_size) {
    const float* x = (const float*)d_in[0];
    const float* w = (const float*)d_in[1];
    float* out = (float*)d_out;

    cudaFuncSetAttribute(bcconv_kernel,
                         cudaFuncAttributeMaxDynamicSharedMemorySize,
                         SMEM_FLOATS * (int)sizeof(float));

    prep_kernel<<<(NQ * NP * NF + 255) / 256, 256>>>(w);
    bcconv_kernel<<<8 * CHUNKS, NTHREADS, SMEM_FLOATS * sizeof(float)>>>(x, out);
}

// round 6
// speedup vs baseline: 1.4940x; 1.1433x over previous
#include <cuda_runtime.h>
#include <math.h>

// x: (8, 256, 32, 32) f32 ; weight: (8, 36, 64) f32 ; out: (8, 512, 32, 32) f32
#define NQ 36
#define NP 8
#define NF 33
#define NW 16              // warps (=rows) per CTA
#define NTHREADS (NW * 32)
#define CHUNKS 64          // 1024 / NW, exact

__device__ float g_WF[NQ * NP * NF * 2];

__global__ void prep_kernel(const float* __restrict__ w) {
    int idx = blockIdx.x * blockDim.x + threadIdx.x;
    if (idx >= NQ * NP * NF) return;
    int f  = idx % NF;
    int pq = idx / NF;
    int p  = pq % NP;
    int q  = pq / NP;
    const float* wp = w + (p * NQ + q) * 64;
    float re = 0.f, im = 0.f;
    for (int m = 0; m < 64; m++) {
        int t = (f * m) & 63;
        float s, c;
        sincosf(-(float)t * 0.0981747704246810387f, &s, &c);
        re = fmaf(wp[m], c, re);
        im = fmaf(wp[m], s, im);
    }
    g_WF[idx * 2]     = re;
    g_WF[idx * 2 + 1] = im;
}

// compile-time twiddles: cos(k*pi/32), k=0..32; sin(k) = cos(|k-16|)
__device__ constexpr float TWC[33] = {
    1.0f, 0.9951847266721969f, 0.9807852804032304f, 0.9569403357322088f,
    0.9238795325112867f, 0.8819212643483551f, 0.8314696123025452f, 0.7730104533627370f,
    0.7071067811865476f, 0.6343932841636455f, 0.5555702330196022f, 0.4713967368259976f,
    0.3826834323650898f, 0.2902846772544624f, 0.1950903220161283f, 0.0980171403295606f,
    0.0f, -0.0980171403295606f, -0.1950903220161283f, -0.2902846772544624f,
    -0.3826834323650898f, -0.4713967368259976f, -0.5555702330196022f, -0.6343932841636455f,
    -0.7071067811865476f, -0.7730104533627370f, -0.8314696123025452f, -0.8819212643483551f,
    -0.9238795325112867f, -0.9569403357322088f, -0.9807852804032304f, -0.9951847266721969f,
    -1.0f };
__device__ constexpr float twc(int k) { return TWC[k]; }
__device__ constexpr float tws(int k) { return TWC[k < 16 ? 16 - k : k - 16]; }

// f32x2 packed helpers
__device__ __forceinline__ unsigned long long ffma2(unsigned long long a,
                                                    unsigned long long b,
                                                    unsigned long long c) {
    unsigned long long d;
    asm("fma.rn.f32x2 %0, %1, %2, %3;" : "=l"(d) : "l"(a), "l"(b), "l"(c));
    return d;
}
__device__ __forceinline__ unsigned long long f2u(float x, float y) {
    unsigned long long v;
    asm("mov.b64 %0, {%1, %2};" : "=l"(v) : "f"(x), "f"(y));
    return v;
}
__device__ __forceinline__ float2 u2f(unsigned long long v) {
    float2 r;
    asm("mov.b64 {%0, %1}, %2;" : "=f"(r.x), "=f"(r.y) : "l"(v));
    return r;
}

// smem float offsets
#define SZ_WF    (NQ * NP * NF * 2)          // 19008
#define U_STRIDE (NQ * 66)                   // 2376 floats per row; XF in-place over xu
#define SZ_U     (NW * U_STRIDE)             // 38016
#define SZ_TW    66                          // 33 x (cos,sin)
#define OFF_WF   0
#define OFF_U    (OFF_WF + SZ_WF)
#define OFF_TW   (OFF_U + SZ_U)
#define SMEM_FLOATS (OFF_TW + SZ_TW)         // 57090 floats = 228360 B

#define YT_STRIDE 522                        // ytile [NW px][522 ch] (522 mod 32 = 10: conflict-free epilogue)

__global__ void __launch_bounds__(NTHREADS, 1)
bcconv_kernel(const float* __restrict__ x, float* __restrict__ out) {
    extern __shared__ float smem[];
    float* sWF = smem + OFF_WF;
    float* sU  = smem + OFF_U;
    float* sTW = smem + OFF_TW;

    const int tid  = threadIdx.x;
    const int wid  = tid >> 5;
    const int lane = tid & 31;
    const int bi   = blockIdx.x;
    const int b    = bi >> 6;
    const int l0   = (bi & 63) * NW;            // first pixel of this CTA
    const int r    = l0 + wid;                  // this warp's pixel row (< 1024 always)

    // twiddle LUT (float2): (cos, sin)(2*pi*k/64), k=0..32
    if (tid < 33) {
        float s, c;
        sincosf((float)tid * 0.0981747704246810387f, &s, &c);
        sTW[2 * tid]     = c;
        sTW[2 * tid + 1] = s;
    }
    // stage frequency weights (float4)
    {
        const float4* src = (const float4*)g_WF;
        float4* dst = (float4*)sWF;
        for (int i = tid; i < SZ_WF / 4; i += NTHREADS) dst[i] = src[i];
    }

    float* xu = sU + wid * U_STRIDE;   // this warp's slice; also XF (in-place)

    // ---------- gather 2304-float flat slice for this warp's row ----------
    {
        int G = r * 2304 + lane;
        int l = G & 1023;
        int i = G >> 10;
        int c = i / 9;
        int t = i - c * 9;
        int t3 = t / 3;
        int dh = t3 - 1, dw = t - t3 * 3 - 1;
        const float* xc = x + ((b << 8) + c) * 1024;
        int j = lane;
#pragma unroll 8
        for (int k = 0; k < 72; ++k) {
            int gh = (l >> 5) + dh;
            int gw = (l & 31) + dw;
            float v = 0.f;
            if ((unsigned)gh < 32u && (unsigned)gw < 32u)
                v = __ldg(xc + (gh << 5) + gw);
            xu[(j >> 6) * 66 + (j & 63)] = v;
            j += 32;
            l += 32;
            if (l >= 1024) {
                l -= 1024;
                if (++t == 9) { t = 0; xc += 1024; }
                t3 = t / 3;
                dh = t3 - 1; dw = t - t3 * 3 - 1;
            }
        }
    }
    __syncthreads();

    // ---------- CTA-wide forward rfft64: 576 blocks over 512 threads ----------
    for (int round = 0; round < 2; round++) {
        int B = round * NTHREADS + tid;
        if (B < NW * NQ) {
            float* base = sU + B * 66;
            float zr[32], zi[32];
            const float2* src = (const float2*)base;
#pragma unroll
            for (int m = 0; m < 32; m++) {
                float2 v = src[m];
                zr[m] = v.x;
                zi[m] = v.y;
            }
#pragma unroll
            for (int s = 0; s < 5; s++) {
                const int half = 16 >> s;
#pragma unroll
                for (int g = 0; g < (1 << s); g++) {
#pragma unroll
                    for (int j = 0; j < half; j++) {
                        int a  = g * (half * 2) + j;
                        int bb = a + half;
                        float tr = zr[a] - zr[bb];
                        float ti = zi[a] - zi[bb];
                        zr[a] += zr[bb];
                        zi[a] += zi[bb];
                        const float c  = twc(j << (s + 1));
                        const float sn = tws(j << (s + 1));
                        zr[bb] = tr * c + ti * sn;
                        zi[bb] = ti * c - tr * sn;
                    }
                }
            }
            constexpr int rev[32] = {0,16,8,24,4,20,12,28,2,18,10,26,6,22,14,30,
                                     1,17,9,25,5,21,13,29,3,19,11,27,7,23,15,31};
            float x32 = zr[0] - zi[0];
            float2* dst = (float2*)base;
#pragma unroll
            for (int k = 0; k < 32; k++) {
                int kc = (32 - k) & 31;
                float Zkr = zr[rev[k]],  Zki = zi[rev[k]];
                float Zcr = zr[rev[kc]], Zci = -zi[rev[kc]];
                float Fer = 0.5f * (Zkr + Zcr);
                float Fei = 0.5f * (Zki + Zci);
                float For = 0.5f * (Zki - Zci);
                float Foi = -0.5f * (Zkr - Zcr);
                const float c  = twc(k);
                const float sn = tws(k);
                dst[k] = make_float2(Fer + c * For + sn * Foi,
                                     Fei + c * Foi - sn * For);
            }
            dst[32] = make_float2(x32, 0.f);
        }
    }
    __syncthreads();

    // ---------- freq matvec (f32x2): hf[p][f=lane] = sum_q xf[q][f] * wf[q][p][f] ----------
    float Xr[NP], Xi[NP], X32[NP];
    {
        unsigned long long accA[NP], accB[NP];
#pragma unroll
        for (int p = 0; p < NP; p++) { accA[p] = 0ull; accB[p] = 0ull; }
        const float2* xf2 = (const float2*)xu;                     // [q*33 + f]
        const unsigned long long* wf8 = (const unsigned long long*)sWF; // [(q*8+p)*33 + f]
        for (int q = 0; q < NQ; q++) {
            float2 xv = xf2[q * 33 + lane];
            unsigned long long xrr = f2u(xv.x, xv.x);
            unsigned long long xii = f2u(xv.y, xv.y);
#pragma unroll
            for (int p = 0; p < NP; p++) {
                unsigned long long wv = wf8[(q * NP + p) * NF + lane];
                accA[p] = ffma2(xrr, wv, accA[p]);   // (xr*wr, xr*wi)
                accB[p] = ffma2(xii, wv, accB[p]);   // (xi*wr, xi*wi)
            }
        }
#pragma unroll
        for (int p = 0; p < NP; p++) {
            float2 A = u2f(accA[p]);
            float2 Bv = u2f(accB[p]);
            Xr[p] = A.x - Bv.y;
            Xi[p] = A.y + Bv.x;
        }
        // f = 32 (pure real): warp xor-reduce over q; result in ALL lanes
#pragma unroll
        for (int p = 0; p < NP; p++) {
            float s = xu[lane * 66 + 64] * sWF[((lane * NP + p) * NF + 32) * 2];
            if (lane < 4) {
                int q2 = lane + 32;
                s += xu[q2 * 66 + 64] * sWF[((q2 * NP + p) * NF + 32) * 2];
            }
#pragma unroll
            for (int o = 16; o > 0; o >>= 1) s += __shfl_xor_sync(0xffffffffu, s, o);
            X32[p] = s;
        }
    }
    __syncthreads();   // all XF reads done -> sU becomes ytile [NW px][YT_STRIDE]

    // ---------- inverse rfft64 via cross-lane FFT32 (lane = freq k) ----------
    {
        float* yt = sU;
        const float2* tw2 = (const float2*)sTW;
        float2 wk = tw2[lane];                    // e^{+2 pi i k/64}
        const int pk = (32 - lane) & 31;
        // stage twiddles (shared across p): W32^j at stage s -> tw64[j << (s+1)]
        float2 stw[5];
#pragma unroll
        for (int s = 0; s < 5; s++) {
            int half = 16 >> s;
            stw[s] = tw2[(lane & (half - 1)) << (s + 1)];
        }
        const int m = __brev(lane) >> 27;         // 5-bit reversal
        float2* ytv = (float2*)yt;
#pragma unroll
        for (int p = 0; p < NP; p++) {
            float xr = Xr[p], xi = Xi[p];
            float xcr = __shfl_sync(0xffffffffu, xr, pk);
            float xci = -__shfl_sync(0xffffffffu, xi, pk);
            if (lane == 0) { xcr = X32[p]; xci = 0.f; }
            float fer = 0.5f * (xr + xcr);
            float fei = 0.5f * (xi + xci);
            float dr  = 0.5f * (xr - xcr);
            float di  = 0.5f * (xi - xci);
            float fo_r = wk.x * dr - wk.y * di;
            float fo_i = wk.x * di + wk.y * dr;
            // Z = Fe + i*Fo ; conj for inverse-via-forward trick
            float vr = fer - fo_i;
            float vi = -(fei + fo_r);
            // forward FFT32 across lanes (DIF, natural-in, bitrev-out)
#pragma unroll
            for (int s = 0; s < 5; s++) {
                int half = 16 >> s;
                float ur = __shfl_xor_sync(0xffffffffu, vr, half);
                float ui = __shfl_xor_sync(0xffffffffu, vi, half);
                float ddr = ur - vr, ddi = ui - vi;
                float tr = ddr * stw[s].x + ddi * stw[s].y;
                float ti = ddi * stw[s].x - ddr * stw[s].y;
                bool upper = (lane & half) != 0;
                vr = upper ? tr : vr + ur;
                vi = upper ? ti : vi + ui;
            }
            // z = conj(F)/32 ; lane holds z[m]: y[2m]=Re, y[2m+1]=-Im
            ytv[wid * (YT_STRIDE / 2) + p * 32 + m] =
                make_float2(vr * 0.03125f, -vi * 0.03125f);
        }
    }
    __syncthreads();

    // ---------- output write: out[b, ch, l0 + px] ----------
    {
        const float* yt = sU;
        float* ob = out + (b * 512) * 1024 + l0;
        const int px  = tid & 15;
        const int ch0 = tid >> 4;
#pragma unroll
        for (int k = 0; k < 16; k++) {
            int ch = ch0 + k * 32;
            ob[ch * 1024 + px] = yt[px * YT_STRIDE + ch];
        }
    }
}

extern "C" void kernel_launch(void* const* d_in, const int* in_sizes, int n_in,
                              void* d_out, int out_size) {
    const float* x = (const float*)d_in[0];
    const float* w = (const float*)d_in[1];
    float* out = (float*)d_out;

    cudaFuncSetAttribute(bcconv_kernel,
                         cudaFuncAttributeMaxDynamicSharedMemorySize,
                         SMEM_FLOATS * (int)sizeof(float));

    prep_kernel<<<(NQ * NP * NF + 255) / 256, 256>>>(w);
    bcconv_kernel<<<8 * CHUNKS, NTHREADS, SMEM_FLOATS * sizeof(float)>>>(x, out);
}